// round 7
// baseline (speedup 1.0000x reference)
#include <cuda_runtime.h>

#define NMAX    131072      // max src index supported by 17-bit packing
#define BV      32          // batch
#define BD      352         // dsts per bucket
#define NBMAX   320         // max buckets (ceil(100000/352) = 285)
#define CAP     16384       // per-bucket record capacity (expected ~11228, sd ~106)
#define SCAT_E  16          // edges per thread in scatter

// Static scratch (no allocations allowed).
__device__ float g_xT[(size_t)NMAX * BV];            // x transposed (N, B)
__device__ int   g_cursor[NBMAX];                    // bucket fill cursors (pre-offset)
__device__ int2  g_edges[(size_t)NBMAX * CAP];       // binned records (src|dlo<<17, val)

// ---------------------------------------------------------------------------
__global__ void init_cursor_kernel(int nbuck) {
    int i = blockIdx.x * blockDim.x + threadIdx.x;
    if (i < nbuck) g_cursor[i] = i * CAP;
}

// Transpose x (B, N) -> g_xT (N, B).
__global__ void transpose_x_kernel(const float* __restrict__ x, int N, int B) {
    __shared__ float tile[32][33];
    int n0 = blockIdx.x * 32;
    int tx = threadIdx.x, ty = threadIdx.y;
    int n = n0 + tx;
    if (ty < B && n < N) tile[ty][tx] = x[(size_t)ty * N + n];
    __syncthreads();
    int nw = n0 + ty;
    if (tx < B && nw < N) g_xT[(size_t)nw * BV + tx] = tile[tx][ty];
}

// ---------------------------------------------------------------------------
// Bin edges by dst bucket. Per block: local smem histogram, one global
// reservation atomic per (block,bucket), then packed-record writes into the
// reserved contiguous ranges.
__global__ __launch_bounds__(1024) void scatter_kernel(
        const int* __restrict__ idx, const float* __restrict__ vals,
        int nnz, int nbuck) {
    __shared__ int sh_cnt [NBMAX];
    __shared__ int sh_base[NBMAX];
    int tid = threadIdx.x;
    for (int t = tid; t < nbuck; t += blockDim.x) sh_cnt[t] = 0;
    __syncthreads();

    long long start = (long long)blockIdx.x * blockDim.x * SCAT_E;
    int bk[SCAT_E];
    int dl[SCAT_E];
    #pragma unroll
    for (int k = 0; k < SCAT_E; k++) {
        long long i = start + (long long)k * blockDim.x + tid;
        if (i < nnz) {
            int d = idx[nnz + i];
            int b = d / BD;
            bk[k] = b;
            dl[k] = d - b * BD;
            atomicAdd(&sh_cnt[b], 1);
        } else {
            bk[k] = -1;
        }
    }
    __syncthreads();
    for (int t = tid; t < nbuck; t += blockDim.x) {
        int c = sh_cnt[t];
        sh_base[t] = c ? atomicAdd(&g_cursor[t], c) : 0;
        sh_cnt[t]  = 0;                    // reuse as local cursor
    }
    __syncthreads();
    #pragma unroll
    for (int k = 0; k < SCAT_E; k++) {
        long long i = start + (long long)k * blockDim.x + tid;
        if (bk[k] >= 0) {
            int loc = atomicAdd(&sh_cnt[bk[k]], 1);
            int src = idx[i];
            int vbits = __float_as_int(vals[i]);
            g_edges[(size_t)sh_base[bk[k]] + loc] =
                make_int2(src | (dl[k] << 17), vbits);
        }
    }
}

// ---------------------------------------------------------------------------
// One CTA per bucket: accumulate edges into a smem tile (no L2 atomics),
// then write the output slice fused with bias (coalesced per batch).
__global__ __launch_bounds__(1024) void accum_kernel(
        float* __restrict__ out, const float* __restrict__ bias, int M, int B) {
    __shared__ float acc[BD * 33];         // padded: bank-conflict-free both ways
    int bkt  = blockIdx.x;
    int tid  = threadIdx.x;
    int lane = tid & 31;
    int wid  = tid >> 5;
    int nthr = blockDim.x;
    int nwarp = nthr >> 5;

    for (int i = tid; i < BD * 33; i += nthr) acc[i] = 0.f;
    __syncthreads();

    int base = bkt * CAP;
    int cnt  = g_cursor[bkt] - base;       // records in this bucket

    for (int i0 = wid * 4; i0 < cnt; i0 += nwarp * 4) {
        int2 r[4];
        #pragma unroll
        for (int u = 0; u < 4; u++)
            r[u] = (i0 + u < cnt) ? g_edges[(size_t)base + i0 + u]
                                  : make_int2(0, 0);
        float xv[4];
        #pragma unroll
        for (int u = 0; u < 4; u++) {
            int src = r[u].x & 0x1FFFF;
            xv[u] = (i0 + u < cnt) ? g_xT[(size_t)src * BV + lane] : 0.f;
        }
        #pragma unroll
        for (int u = 0; u < 4; u++) {
            if (i0 + u < cnt) {
                int dlo = r[u].x >> 17;
                atomicAdd(&acc[dlo * 33 + lane], __int_as_float(r[u].y) * xv[u]);
            }
        }
    }
    __syncthreads();

    int dst0 = bkt * BD;
    int ndst = min(BD, M - dst0);
    int tot  = ndst * B;
    for (int i = tid; i < tot; i += nthr) {
        int b = i / ndst;
        int m = i - b * ndst;
        out[(size_t)b * M + dst0 + m] = acc[m * 33 + b] + __ldg(bias + dst0 + m);
    }
}

// ---------------------------------------------------------------------------
extern "C" void kernel_launch(void* const* d_in, const int* in_sizes, int n_in,
                              void* d_out, int out_size) {
    const float* x    = (const float*)d_in[0];   // (B, N, 1)
    const int*   idx  = (const int*)  d_in[1];   // (2, NNZ): row0=src, row1=dst
    const float* vals = (const float*)d_in[2];   // (NNZ,)
    const float* bias = (const float*)d_in[3];   // (M, 1)
    float*       out  = (float*)d_out;           // (B, M, 1)

    int M   = in_sizes[3];
    int NNZ = in_sizes[1] / 2;
    int B   = out_size / M;
    int N   = in_sizes[0] / B;
    int nbuck = (M + BD - 1) / BD;               // 285 for M=100000

    init_cursor_kernel<<<(nbuck + 255) / 256, 256>>>(nbuck);

    {
        dim3 blk(32, 32);
        transpose_x_kernel<<<(N + 31) / 32, blk>>>(x, N, B);
    }

    {
        long long per_block = 1024LL * SCAT_E;
        int blocks = (int)((NNZ + per_block - 1) / per_block);
        scatter_kernel<<<blocks, 1024>>>(idx, vals, NNZ, nbuck);
    }

    accum_kernel<<<nbuck, 1024>>>(out, bias, M, B);
}